// round 15
// baseline (speedup 1.0000x reference)
#include <cuda_runtime.h>

// B = 262144, n_in = 128, n_middle = 512, n_extra = 2
// Inputs: x [B,128] f32, w [B,1] f32, p [1,2] f32,
//         W_in [512,130] f32, W_out [128,512] f32
// Output: [B,128] f32 = x + o (o is a broadcast row)
//
// Math: weighted_avg commutes with the linear maps; second weighted_avg of a
// constant row is identity:
//   v = sum_b w_b * x_b ; s = sum_b w_b ; xbar = [v/s, p]
//   h = relu(W_in @ xbar) ; o = W_out @ h ; out = x + o

#define N_IN   128
#define N_CAT  130
#define N_MID  512
#define NBLK   1024
#define PSTR   132   // partial row stride (floats); 528 B rows, 16B-aligned

#define W_IN_BYTES  (N_MID * N_CAT * 4)   // 266240
#define W_OUT_BYTES (N_IN * N_MID * 4)    // 262144

#define K2_GRID    1184     // 4 exact waves at 2 blocks/SM on 148 SMs
#define K2_THREADS 1024

__device__ __align__(16) float g_part[NBLK * PSTR];   // [block][col 0..127]
__device__ __align__(16) float g_wpart[NBLK];         // per-block sum(w)
__device__ __align__(16) float g_o[N_IN];             // broadcast row
__device__ int g_done   = 0;                          // gate flag (self-resetting)
__device__ int g_passed = 0;                          // gate-exit ticket

__device__ __forceinline__ void fma4(float4& a, float s, const float4& v) {
    a.x = fmaf(s, v.x, a.x);
    a.y = fmaf(s, v.y, a.y);
    a.z = fmaf(s, v.z, a.z);
    a.w = fmaf(s, v.w, a.w);
}

__device__ __forceinline__ float warp_sum(float v) {
    #pragma unroll
    for (int off = 16; off; off >>= 1)
        v += __shfl_down_sync(0xffffffffu, v, off);
    return v;
}

__device__ __forceinline__ void prefetch_l2(const void* p) {
    asm volatile("prefetch.global.L2 [%0];" :: "l"(p));
}

// ---------------------------------------------------------------------------
// K1: per-block weighted column sums (unroll 2 — measured best). The LAST 32
// blocks (final wave) prefetch W_in/W_out into L2 so the fused mid in k2
// reads warm weights. prefetch has no dest reg -> no occupancy cost.
// ---------------------------------------------------------------------------
__global__ void __launch_bounds__(256)
k1_partial(const float* __restrict__ x, const float* __restrict__ w,
           const float* __restrict__ W_in, const float* __restrict__ W_out, int B)
{
    const int t  = threadIdx.x;
    const int c4 = t & 31;            // float4 column (0..31)
    const int rg = t >> 5;            // warp id (0..7)
    const int rowsPerBlk = B / NBLK;  // 256
    const int r0 = blockIdx.x * rowsPerBlk;
    const int nG = rowsPerBlk >> 5;   // 8 groups of 4 rows per warp

    if (blockIdx.x >= NBLK - 32) {
        const int idx  = (blockIdx.x - (NBLK - 32)) * 256 + t;
        const int byte = idx * 128;
        if (byte < W_IN_BYTES)
            prefetch_l2((const char*)W_in + byte);
        else if (byte - W_IN_BYTES < W_OUT_BYTES)
            prefetch_l2((const char*)W_out + (byte - W_IN_BYTES));
    }

    const float4* __restrict__ x4  = (const float4*)x;
    const float4* __restrict__ w4p = (const float4*)w;

    float4 acc = make_float4(0.f, 0.f, 0.f, 0.f);
    float  sw  = 0.f;

    #pragma unroll 2
    for (int g = 0; g < nG; g++) {
        const int rbase = r0 + rg * 4 + g * 32;
        const float4 wv = __ldg(&w4p[rbase >> 2]);
        const long base = (long)rbase * 32 + c4;
        float4 a0 = x4[base];
        float4 a1 = x4[base + 32];
        float4 a2 = x4[base + 64];
        float4 a3 = x4[base + 96];
        fma4(acc, wv.x, a0);
        fma4(acc, wv.y, a1);
        fma4(acc, wv.z, a2);
        fma4(acc, wv.w, a3);
        sw += (wv.x + wv.y) + (wv.z + wv.w);
    }

    __shared__ __align__(16) float s_v[8][N_IN];
    __shared__ float s_w[8];
    ((float4*)s_v[rg])[c4] = acc;
    if (c4 == 0) s_w[rg] = sw;
    __syncthreads();

    if (t < N_IN) {
        float vs = 0.f;
        #pragma unroll
        for (int g = 0; g < 8; g++) vs += s_v[g][t];
        g_part[blockIdx.x * PSTR + t] = vs;      // coalesced 512B per block
    } else if (t == N_IN) {
        float ws = 0.f;
        #pragma unroll
        for (int g = 0; g < 8; g++) ws += s_w[g];
        g_wpart[blockIdx.x] = ws;
    }
}

// ---------------------------------------------------------------------------
// K2 (fused): block 0 computes the mid pipeline (reduce + matvecs -> g_o),
// sets g_done; all other blocks gate on g_done (volatile poll + nanosleep —
// NOT atomics, to avoid same-address atomic-ALU serialization), then everyone
// streams out = x + o. Ticket reset makes the flags replay-safe.
// __launch_bounds__(1024, 2) caps regs at 32 so the mid path cannot poison
// streaming-block occupancy (mid spills, if any, hit one block only).
// ---------------------------------------------------------------------------
__global__ void __launch_bounds__(K2_THREADS, 2)
k2_fused(const float* __restrict__ x, float* __restrict__ out, long n4,
         const float* __restrict__ p, const float* __restrict__ W_in,
         const float* __restrict__ W_out)
{
    const int t    = threadIdx.x;
    const int lane = t & 31;
    const int wid  = t >> 5;          // 0..31

    __shared__ __align__(16) float4 s_o[32];

    if (blockIdx.x == 0) {
        // ---------------- mid pipeline (identical to proven k1b) ----------
        __shared__ float s_red[32][129];   // 129 stride -> conflict-free cols
        __shared__ float s_wp[32];
        __shared__ float s_xbar[N_CAT];
        __shared__ float s_h[N_MID];
        __shared__ float s_stot;

        // a) group g sums blocks [g*32, g*32+32); one float4 col per thread
        {
            const int g  = wid;
            const int c4 = lane;
            const int b0 = g * (NBLK / 32);
            float4 a = make_float4(0.f, 0.f, 0.f, 0.f);
            #pragma unroll 8
            for (int b = 0; b < NBLK / 32; b++) {
                const float4 v = *(const float4*)&g_part[(b0 + b) * PSTR + 4 * c4];
                a.x += v.x; a.y += v.y; a.z += v.z; a.w += v.w;
            }
            s_red[g][4 * c4 + 0] = a.x;
            s_red[g][4 * c4 + 1] = a.y;
            s_red[g][4 * c4 + 2] = a.z;
            s_red[g][4 * c4 + 3] = a.w;
        }
        {
            float s = warp_sum(g_wpart[t]);
            if (lane == 0) s_wp[wid] = s;
        }
        __syncthreads();

        if (wid == 0) {
            float s = warp_sum(s_wp[lane]);
            if (lane == 0) s_stot = s;
        }
        __syncthreads();

        if (t < N_IN) {
            float v = 0.f;
            #pragma unroll
            for (int g = 0; g < 32; g++) v += s_red[g][t];
            s_xbar[t] = v / s_stot;
        } else if (t < N_CAT) {
            s_xbar[t] = p[t - N_IN];
        }
        __syncthreads();

        // c) h = relu(W_in @ xbar): 512 rows / 32 warps
        #pragma unroll 4
        for (int r = wid; r < N_MID; r += 32) {
            const float* __restrict__ row = W_in + (long)r * N_CAT;
            float acc = 0.f;
            #pragma unroll
            for (int k = lane; k < N_CAT; k += 32)
                acc = fmaf(row[k], s_xbar[k], acc);
            acc = warp_sum(acc);
            if (lane == 0) s_h[r] = fmaxf(acc, 0.f);
        }
        __syncthreads();

        // d) o = W_out @ h: 128 rows / 32 warps
        #pragma unroll
        for (int r = wid; r < N_IN; r += 32) {
            const float* __restrict__ row = W_out + (long)r * N_MID;
            float acc = 0.f;
            #pragma unroll
            for (int k = lane; k < N_MID; k += 32)
                acc = fmaf(row[k], s_h[k], acc);
            acc = warp_sum(acc);
            if (lane == 0) g_o[r] = acc;
        }
        __threadfence();              // g_o visible before flag
        __syncthreads();
        if (t == 0) atomicExch(&g_done, 1);
    } else {
        // gate: cheap volatile polls (L2 reads, no atomic serialization)
        if (t == 0) {
            while (*(volatile int*)&g_done == 0) __nanosleep(128);
        }
        __syncthreads();
        __threadfence();              // order subsequent g_o reads
    }

    // every block (incl. 0): stage o, then stream
    if (t < 32) s_o[t] = ((const float4*)g_o)[t];
    __syncthreads();

    const float4* __restrict__ x4 = (const float4*)x;
    float4* __restrict__ o4 = (float4*)out;

    const long stride = (long)K2_GRID * K2_THREADS;
    for (long i = (long)blockIdx.x * K2_THREADS + t; i < n4; i += stride) {
        float4 xv = __ldcs(&x4[i]);
        float4 ov = s_o[i & 31];
        xv.x += ov.x; xv.y += ov.y; xv.z += ov.z; xv.w += ov.w;
        __stcs(&o4[i], xv);
    }

    // replay-safe reset: the LAST block to finish clears both flags.
    __syncthreads();
    if (t == 0) {
        int n = atomicAdd(&g_passed, 1);
        if (n == (int)gridDim.x - 1) {
            g_passed = 0;
            atomicExch(&g_done, 0);
        }
    }
}

// ---------------------------------------------------------------------------
extern "C" void kernel_launch(void* const* d_in, const int* in_sizes, int n_in,
                              void* d_out, int out_size)
{
    const float* x     = (const float*)d_in[0];
    const float* w     = (const float*)d_in[1];
    const float* p     = (const float*)d_in[2];
    const float* W_in  = (const float*)d_in[3];
    const float* W_out = (const float*)d_in[4];
    float*       out   = (float*)d_out;

    const int  B  = in_sizes[0] / N_IN;
    const long n4 = (long)B * (N_IN / 4);

    k1_partial<<<NBLK, 256>>>(x, w, W_in, W_out, B);
    k2_fused<<<K2_GRID, K2_THREADS>>>(x, out, n4, p, W_in, W_out);
}

// round 16
// speedup vs baseline: 1.1270x; 1.1270x over previous
#include <cuda_runtime.h>

// B = 262144, n_in = 128, n_middle = 512, n_extra = 2
// Inputs: x [B,128] f32, w [B,1] f32, p [1,2] f32,
//         W_in [512,130] f32, W_out [128,512] f32
// Output: [B,128] f32 = x + o (o is a broadcast row)
//
// Math: weighted_avg commutes with the linear maps; second weighted_avg of a
// constant row is identity:
//   v = sum_b w_b * x_b ; s = sum_b w_b ; xbar = [v/s, p]
//   h = relu(W_in @ xbar) ; o = W_out @ h ; out = x + o

#define N_IN   128
#define N_CAT  130
#define N_MID  512
#define NBLK   512   // fewer, fatter k1 blocks -> half the partial traffic for k1b
#define PSTR   132   // partial row stride (floats); 528 B rows, 16B-aligned

#define W_IN_BYTES  (N_MID * N_CAT * 4)   // 266240
#define W_OUT_BYTES (N_IN * N_MID * 4)    // 262144

__device__ __align__(16) float g_part[NBLK * PSTR];   // [block][col 0..127]
__device__ __align__(16) float g_wpart[NBLK];         // per-block sum(w)
__device__ __align__(16) float g_o[N_IN];             // broadcast row

__device__ __forceinline__ void fma4(float4& a, float s, const float4& v) {
    a.x = fmaf(s, v.x, a.x);
    a.y = fmaf(s, v.y, a.y);
    a.z = fmaf(s, v.z, a.z);
    a.w = fmaf(s, v.w, a.w);
}

__device__ __forceinline__ float warp_sum(float v) {
    #pragma unroll
    for (int off = 16; off; off >>= 1)
        v += __shfl_down_sync(0xffffffffu, v, off);
    return v;
}

__device__ __forceinline__ void prefetch_l2(const void* p) {
    asm volatile("prefetch.global.L2 [%0];" :: "l"(p));
}

// ---------------------------------------------------------------------------
// K1: per-block weighted column sums (unroll 2 — measured best). The LAST 32
// blocks prefetch W_in/W_out into L2 at the end of k1 so k1b reads warm
// weights. prefetch has no dest reg -> no occupancy cost.
// ---------------------------------------------------------------------------
__global__ void __launch_bounds__(256)
k1_partial(const float* __restrict__ x, const float* __restrict__ w,
           const float* __restrict__ W_in, const float* __restrict__ W_out, int B)
{
    const int t  = threadIdx.x;
    const int c4 = t & 31;            // float4 column (0..31)
    const int rg = t >> 5;            // warp id (0..7)
    const int rowsPerBlk = B / NBLK;  // 512
    const int r0 = blockIdx.x * rowsPerBlk;
    const int nG = rowsPerBlk >> 5;   // 16 groups of 4 rows per warp

    if (blockIdx.x >= NBLK - 32) {
        const int idx  = (blockIdx.x - (NBLK - 32)) * 256 + t;
        const int byte = idx * 128;
        if (byte < W_IN_BYTES)
            prefetch_l2((const char*)W_in + byte);
        else if (byte - W_IN_BYTES < W_OUT_BYTES)
            prefetch_l2((const char*)W_out + (byte - W_IN_BYTES));
    }

    const float4* __restrict__ x4  = (const float4*)x;
    const float4* __restrict__ w4p = (const float4*)w;

    float4 acc = make_float4(0.f, 0.f, 0.f, 0.f);
    float  sw  = 0.f;

    #pragma unroll 2
    for (int g = 0; g < nG; g++) {
        const int rbase = r0 + rg * 4 + g * 32;
        const float4 wv = __ldg(&w4p[rbase >> 2]);
        const long base = (long)rbase * 32 + c4;
        float4 a0 = x4[base];
        float4 a1 = x4[base + 32];
        float4 a2 = x4[base + 64];
        float4 a3 = x4[base + 96];
        fma4(acc, wv.x, a0);
        fma4(acc, wv.y, a1);
        fma4(acc, wv.z, a2);
        fma4(acc, wv.w, a3);
        sw += (wv.x + wv.y) + (wv.z + wv.w);
    }

    __shared__ __align__(16) float s_v[8][N_IN];
    __shared__ float s_w[8];
    ((float4*)s_v[rg])[c4] = acc;
    if (c4 == 0) s_w[rg] = sw;
    __syncthreads();

    if (t < N_IN) {
        float vs = 0.f;
        #pragma unroll
        for (int g = 0; g < 8; g++) vs += s_v[g][t];
        g_part[blockIdx.x * PSTR + t] = vs;      // coalesced 512B per block
    } else if (t == N_IN) {
        float ws = 0.f;
        #pragma unroll
        for (int g = 0; g < 8; g++) ws += s_w[g];
        g_wpart[blockIdx.x] = ws;
    }
}

// ---------------------------------------------------------------------------
// K1b: one block, 1024 threads (32 warps). W is L2-hot from k1's tail.
//   a) float4 column reduce of g_part (32 groups x 16 blocks, chain depth 16)
//   b) xbar = [v/s, p]
//   c) h = relu(W_in @ xbar), warp-per-row
//   d) o = W_out @ h, warp-per-row
// ---------------------------------------------------------------------------
__global__ void __launch_bounds__(1024)
k1b_mid(const float* __restrict__ p, const float* __restrict__ W_in,
        const float* __restrict__ W_out)
{
    const int t    = threadIdx.x;
    const int lane = t & 31;
    const int wid  = t >> 5;          // 0..31

    __shared__ float s_red[32][129];   // 129 stride -> conflict-free column sums
    __shared__ float s_wp[16];
    __shared__ float s_xbar[N_CAT];
    __shared__ float s_h[N_MID];
    __shared__ float s_stot;

    // a) group g sums blocks [g*16, g*16+16); one float4 col per thread
    {
        const int g  = wid;
        const int c4 = lane;
        const int b0 = g * (NBLK / 32);      // 16 blocks per group
        float4 a = make_float4(0.f, 0.f, 0.f, 0.f);
        #pragma unroll
        for (int b = 0; b < NBLK / 32; b++) {
            const float4 v = *(const float4*)&g_part[(b0 + b) * PSTR + 4 * c4];
            a.x += v.x; a.y += v.y; a.z += v.z; a.w += v.w;
        }
        s_red[g][4 * c4 + 0] = a.x;
        s_red[g][4 * c4 + 1] = a.y;
        s_red[g][4 * c4 + 2] = a.z;
        s_red[g][4 * c4 + 3] = a.w;
    }
    // wsum: 512 partials, threads 0..511
    {
        float s = (t < NBLK) ? g_wpart[t] : 0.f;
        s = warp_sum(s);
        if (lane == 0 && wid < 16) s_wp[wid] = s;
    }
    __syncthreads();

    if (wid == 0) {
        float s = (lane < 16) ? s_wp[lane] : 0.f;
        s = warp_sum(s);
        if (lane == 0) s_stot = s;
    }
    __syncthreads();

    if (t < N_IN) {
        float v = 0.f;
        #pragma unroll
        for (int g = 0; g < 32; g++) v += s_red[g][t];
        s_xbar[t] = v / s_stot;
    } else if (t < N_CAT) {
        s_xbar[t] = p[t - N_IN];
    }
    __syncthreads();

    // c) h = relu(W_in @ xbar): 512 rows / 32 warps
    #pragma unroll 4
    for (int r = wid; r < N_MID; r += 32) {
        const float* __restrict__ row = W_in + (long)r * N_CAT;
        float acc = 0.f;
        #pragma unroll
        for (int k = lane; k < N_CAT; k += 32)
            acc = fmaf(row[k], s_xbar[k], acc);
        acc = warp_sum(acc);
        if (lane == 0) s_h[r] = fmaxf(acc, 0.f);
    }
    __syncthreads();

    // d) o = W_out @ h: 128 rows / 32 warps
    #pragma unroll
    for (int r = wid; r < N_IN; r += 32) {
        const float* __restrict__ row = W_out + (long)r * N_MID;
        float acc = 0.f;
        #pragma unroll
        for (int k = lane; k < N_MID; k += 32)
            acc = fmaf(row[k], s_h[k], acc);
        acc = warp_sum(acc);
        if (lane == 0) g_o[r] = acc;
    }
}

// ---------------------------------------------------------------------------
// K2: out = x + o. EXACT R8/R9 form (measured 44.96us ~= the LTS-cap floor
// for 268MB; L2 reuse cannot beat it — LTS cap is path-independent).
// ---------------------------------------------------------------------------
__global__ void __launch_bounds__(256)
k2_add(const float* __restrict__ x, float* __restrict__ out, long n4)
{
    __shared__ __align__(16) float4 s_o[32];
    const int t = threadIdx.x;
    if (t < 32) s_o[t] = ((const float4*)g_o)[t];
    __syncthreads();

    const float4* __restrict__ x4 = (const float4*)x;
    float4* __restrict__ o4 = (float4*)out;

    const long stride = (long)gridDim.x * blockDim.x;
    for (long i = (long)blockIdx.x * blockDim.x + t; i < n4; i += stride) {
        float4 xv = __ldcs(&x4[i]);
        float4 ov = s_o[i & 31];
        xv.x += ov.x; xv.y += ov.y; xv.z += ov.z; xv.w += ov.w;
        __stcs(&o4[i], xv);
    }
}

// ---------------------------------------------------------------------------
extern "C" void kernel_launch(void* const* d_in, const int* in_sizes, int n_in,
                              void* d_out, int out_size)
{
    const float* x     = (const float*)d_in[0];
    const float* w     = (const float*)d_in[1];
    const float* p     = (const float*)d_in[2];
    const float* W_in  = (const float*)d_in[3];
    const float* W_out = (const float*)d_in[4];
    float*       out   = (float*)d_out;

    const int  B  = in_sizes[0] / N_IN;
    const long n4 = (long)B * (N_IN / 4);

    k1_partial<<<NBLK, 256>>>(x, w, W_in, W_out, B);
    k1b_mid<<<1, 1024>>>(p, W_in, W_out);
    k2_add<<<4096, 256>>>(x, out, n4);
}